// round 17
// baseline (speedup 1.0000x reference)
#include <cuda_runtime.h>
#include <cstdint>

#define TT   1000
#define TM1  999
#define BB   64

__device__ __align__(16) float g_tau[256], g_lam[256], g_AtL[256], g_AtLA[256];
__device__ float g_tau_mu[16], g_AtLb[16], g_Lb[16];
__device__ float g_consts[2];
__device__ unsigned g_keys[BB][2];

__device__ __align__(16) float g_scr1[(size_t)BB * TM1 * 256]; // fwd: Pi -> bwd: K^T
__device__ __align__(16) float g_scr2[(size_t)BB * TM1 * 256]; // fwd: G  -> bwd: Ls
__device__ __align__(16) float g_scr3[(size_t)BB * TT  * 16];  // fwd: Mim-> bwd: m_t
__device__ __align__(16) float g_eps [(size_t)BB * TT  * 16];

__device__ __forceinline__ void tf2x32(unsigned k0, unsigned k1,
                                       unsigned x0, unsigned x1,
                                       unsigned &o0, unsigned &o1) {
    unsigned ks2 = k0 ^ k1 ^ 0x1BD11BDAu;
    x0 += k0; x1 += k1;
#define TFR(r) { x0 += x1; x1 = (x1 << (r)) | (x1 >> (32 - (r))); x1 ^= x0; }
    TFR(13) TFR(15) TFR(26) TFR(6)
    x0 += k1;  x1 += ks2 + 1u;
    TFR(17) TFR(29) TFR(16) TFR(24)
    x0 += ks2; x1 += k0 + 2u;
    TFR(13) TFR(15) TFR(26) TFR(6)
    x0 += k0;  x1 += k1 + 3u;
    TFR(17) TFR(29) TFR(16) TFR(24)
    x0 += k1;  x1 += ks2 + 4u;
    TFR(13) TFR(15) TFR(26) TFR(6)
    x0 += ks2; x1 += k0 + 5u;
#undef TFR
    o0 = x0; o1 = x1;
}

__device__ __forceinline__ float4 ld4(const float* p) {
    return *reinterpret_cast<const float4*>(p);
}
__device__ __forceinline__ void st4(float* p, float4 v) {
    *reinterpret_cast<float4*>(p) = v;
}
__device__ __forceinline__ void ld8(const float* p, float* r) {
    float4 a = ld4(p), b = ld4(p + 4);
    r[0]=a.x; r[1]=a.y; r[2]=a.z; r[3]=a.w;
    r[4]=b.x; r[5]=b.y; r[6]=b.z; r[7]=b.w;
}
__device__ __forceinline__ void st8(float* p, const float* r) {
    st4(p,     make_float4(r[0], r[1], r[2], r[3]));
    st4(p + 4, make_float4(r[4], r[5], r[6], r[7]));
}

// ---- blocked GJ, 2 pivots [k,k+1]; 32 threads, thread=(row i, 8 cols j0..j0+7) ----
// k is a compile-time literal at every call site (forceinline folds it).
template <bool WITH_M>
__device__ __forceinline__ float gj2(const float (*C)[48], float (*N)[48],
                                     int k, int i, int j0, int q) {
    float p00 = C[k][k],     p01 = C[k][k + 1];
    float p10 = C[k + 1][k], p11 = C[k + 1][k + 1];
    float det = p00 * p11 - p01 * p10;
    float id  = __fdividef(1.f, det);
    float Di00 =  p11 * id, Di01 = -p01 * id;
    float Di10 = -p10 * id, Di11 =  p00 * id;
    float u0 = C[i][k], u1 = C[i][k + 1];
    bool ik = (i == k), ik1 = (i == k + 1);

    // left 8 cols
    {
        float a[8], b0[8], b1[8], res[8];
        ld8(&C[i][j0], a);
        ld8(&C[k][j0], b0);
        ld8(&C[k + 1][j0], b1);
#pragma unroll
        for (int c = 0; c < 8; ++c) {
            float w0 = Di00 * b0[c] + Di01 * b1[c];
            float w1 = Di10 * b0[c] + Di11 * b1[c];
            res[c] = ik ? w0 : (ik1 ? w1 : a[c] - (u0 * w0 + u1 * w1));
        }
        if (q == (k >> 3)) {
            int kc = k & 7;
#pragma unroll
            for (int c = 0; c < 8; ++c) {
                if (c == kc)
                    res[c] = ik ? Di00 : (ik1 ? Di10 : -(u0 * Di00 + u1 * Di10));
                else if (c == kc + 1)
                    res[c] = ik ? Di01 : (ik1 ? Di11 : -(u0 * Di01 + u1 * Di11));
            }
        }
        st8(&N[i][j0], res);
    }
    // right 8 cols (never pivot)
    {
        float a[8], b0[8], b1[8], res[8];
        ld8(&C[i][16 + j0], a);
        ld8(&C[k][16 + j0], b0);
        ld8(&C[k + 1][16 + j0], b1);
#pragma unroll
        for (int c = 0; c < 8; ++c) {
            float w0 = Di00 * b0[c] + Di01 * b1[c];
            float w1 = Di10 * b0[c] + Di11 * b1[c];
            res[c] = ik ? w0 : (ik1 ? w1 : a[c] - (u0 * w0 + u1 * w1));
        }
        st8(&N[i][16 + j0], res);
    }
    if (WITH_M && q == 0) {
        float b0 = C[k][32], b1 = C[k + 1][32], am = C[i][32];
        float w0 = Di00 * b0 + Di01 * b1;
        float w1 = Di10 * b0 + Di11 * b1;
        N[i][32] = ik ? w0 : (ik1 ? w1 : am - (u0 * w0 + u1 * w1));
    }
    __syncwarp();
    return det;
}

// ---- blocked Cholesky (lower), 2 cols [k,k+1]; writes left 16 cols ----
__device__ __forceinline__ void chol2(const float (*C)[48], float (*N)[48],
                                      int k, int i, int j0) {
    float r0  = rsqrtf(C[k][k]);
    float l10 = C[k + 1][k] * r0;
    float t11 = C[k + 1][k + 1] - l10 * l10;
    float r1  = rsqrtf(t11);
    float p0 = C[i][k] * r0;
    float p1 = (C[i][k + 1] - p0 * l10) * r1;
    float a[8], res[8];
    ld8(&C[i][j0], a);
#pragma unroll
    for (int c = 0; c < 8; ++c) {
        int j = j0 + c;
        float r = a[c];
        if (j == k)          { if (i >= k)     r = p0; }
        else if (j == k + 1) { if (i >= k + 1) r = p1; }
        else if (j > k + 1 && i >= j) {
            float q0 = C[j][k] * r0;
            float q1 = (C[j][k + 1] - q0 * l10) * r1;
            r = r - p0 * q0 - p1 * q1;
        }
        res[c] = r;
    }
    st8(&N[i][j0], res);
    __syncwarp();
}

__device__ float logdet16_local(const float M[16][17]) {
    float a[16][16];
    for (int r = 0; r < 16; ++r)
        for (int c = 0; c < 16; ++c) a[r][c] = M[r][c];
    float ld = 0.f;
    for (int k = 0; k < 16; ++k) {
        float p = a[k][k];
        ld += logf(p);
        float pi_ = __fdiv_rn(1.f, p);
        for (int r = k + 1; r < 16; ++r) {
            float f = a[r][k] * pi_;
            for (int c = k + 1; c < 16; ++c) a[r][c] = fmaf(-f, a[k][c], a[r][c]);
        }
    }
    return ld;
}

__global__ void __launch_bounds__(256) setup_kernel(const float* __restrict__ loc,
                                                    const float* __restrict__ Tau_p,
                                                    const float* __restrict__ Lam_p,
                                                    const float* __restrict__ X) {
    __shared__ float sTau[16][17], sLamS[16][17], sA[16][17], sAtLs[16][17];
    __shared__ float sbv[16], slocv[16];
    int tid = threadIdx.x, i = tid >> 4, j = tid & 15;

    float t = 0.f, l = 0.f;
#pragma unroll
    for (int k = 0; k < 16; ++k) {
        t = fmaf(Tau_p[i * 16 + k], Tau_p[j * 16 + k], t);
        l = fmaf(Lam_p[i * 16 + k], Lam_p[j * 16 + k], l);
    }
    if (i == j) { t += 1e-8f; l += 1e-8f; }
    sTau[i][j] = t; sLamS[i][j] = l;
    sA[i][j]   = X[i * 17 + j];
    if (tid < 16) { sbv[tid] = X[tid * 17 + 16]; slocv[tid] = loc[tid]; }
    __syncthreads();

    float atl = 0.f;
#pragma unroll
    for (int k = 0; k < 16; ++k) atl = fmaf(sA[k][i], sLamS[k][j], atl);
    sAtLs[i][j] = atl;
    __syncthreads();

    float atla = 0.f;
#pragma unroll
    for (int k = 0; k < 16; ++k) atla = fmaf(sAtLs[i][k], sA[k][j], atla);

    g_tau[tid] = t; g_lam[tid] = l; g_AtL[tid] = atl; g_AtLA[tid] = atla;

    if (tid < 16) {
        float tm = 0.f, alb = 0.f, lb = 0.f;
#pragma unroll
        for (int k = 0; k < 16; ++k) {
            tm  = fmaf(sTau[tid][k],  slocv[k], tm);
            alb = fmaf(sAtLs[tid][k], sbv[k],   alb);
            lb  = fmaf(sLamS[tid][k], sbv[k],   lb);
        }
        g_tau_mu[tid] = tm; g_AtLb[tid] = alb; g_Lb[tid] = lb;
    }
    if (tid < BB) {
        unsigned o0, o1;
        tf2x32(0u, 42u, 0u, (unsigned)tid, o0, o1);
        g_keys[tid][0] = o0; g_keys[tid][1] = o1;
    }
    __syncthreads();
    if (tid == 0) {
        float ldl = logdet16_local(sLamS);
        float ldt = logdet16_local(sTau);
        float bLb = 0.f, ltm = 0.f;
        for (int k = 0; k < 16; ++k) {
            bLb = fmaf(sbv[k],   g_Lb[k],     bLb);
            ltm = fmaf(slocv[k], g_tau_mu[k], ltm);
        }
        g_consts[0] = -0.5f * bLb + 0.5f * ldl;
        g_consts[1] = -0.5f * ltm + 0.5f * ldt;
    }
}

// =================== main: 32 threads (1 warp) per batch ===================
__global__ void __launch_bounds__(32, 1) lds_main(const float* __restrict__ Jr,
                                                  const float* __restrict__ hr,
                                                  float* __restrict__ out) {
    const int b   = blockIdx.x;
    const int tid = threadIdx.x;
    const int i   = tid >> 1;        // row 0..15
    const int q   = tid & 1;         // col half
    const int j0  = q * 8;
    const bool isq0   = (q == 0);
    const bool isdiag = (q == (i >> 3));   // owns diag element (i,i)

    const float trans_const = g_consts[0];
    const float init_const  = g_consts[1];

    const float* Jb = Jr + (size_t)b * TT * 16;
    const float* Hb = hr + (size_t)b * TT * 16;
    float* scr1 = g_scr1 + (size_t)b * TM1 * 256;
    float* scr2 = g_scr2 + (size_t)b * TM1 * 256;
    float* scr3 = g_scr3 + (size_t)b * TT * 16;
    float* epsb = g_eps  + (size_t)b * TT * 16;

    const size_t KL_OFF    = (size_t)BB * TT * 16;
    const size_t EXXT_OFF  = KL_OFF + BB;
    const size_t EX_OFF    = EXXT_OFF + (size_t)BB * TT * 256;
    const size_t EXXNT_OFF = EX_OFF + (size_t)BB * TT * 16;
    float* zO     = out + (size_t)b * TT * 16;
    float* exxtO  = out + EXXT_OFF + (size_t)b * TT * 256;
    float* exO    = out + EX_OFF + (size_t)b * TT * 16;
    float* exxntO = out + EXXNT_OFF + (size_t)b * TM1 * 256;

    __shared__ __align__(16) float Buf0[16][48], Buf1[16][48];
    __shared__ __align__(16) float sAtL[16][20];
    __shared__ __align__(16) float Gm[16][20], Wb[16][20], Vn[16][20];
    __shared__ __align__(16) float mt_s[16], mn[16], mT_s[16];
    __shared__ __align__(16) float xs[2][16];
    __shared__ float red[32];

    // ---- epsilon generation ----
    {
        unsigned k0 = g_keys[b][0], k1 = g_keys[b][1];
        for (int idx = tid; idx < TT * 16; idx += 32) {
            unsigned o0, o1;
            tf2x32(k0, k1, 0u, (unsigned)idx, o0, o1);
            unsigned bits = o0 ^ o1;
            float f = __uint_as_float((bits >> 9) | 0x3f800000u) - 1.0f;
            const float lo = -0.99999994f;
            float v = fmaxf(lo, f * 2.0f + lo);
            epsb[idx] = 1.4142135623730951f * erfinvf(v);
        }
    }

    // ---- constants (registers, 8 floats per thread) ----
    float lam8[8], atla8[8], atl8[8];
    ld8(&g_lam [i * 16 + j0], lam8);
    ld8(&g_AtLA[i * 16 + j0], atla8);
    ld8(&g_AtL [i * 16 + j0], atl8);
    st8(&sAtL[i][j0], atl8);
    const float lb_r   = g_Lb[i];
    const float atlb_r = g_AtLb[i];

    float lzall = 0.f, lzp = 0.f, klacc = 0.f;
    float jn_r = 0.f, hn_r = 0.f, mv_r = 0.f;

    // ---- pre-stage step 0 ----
    {
        float tau8[8], m0[8];
        ld8(&g_tau[i * 16 + j0], tau8);
        if (isdiag) {
            float jd = Jb[i] + 0.5f;
#pragma unroll
            for (int c = 0; c < 8; ++c) if (j0 + c == i) tau8[c] += jd;
        }
#pragma unroll
        for (int c = 0; c < 8; ++c) m0[c] = tau8[c] + atla8[c];
        st8(&Buf0[i][j0], m0);
        st8(&Buf0[i][16 + j0], atl8);
        if (isq0) {
            mv_r = g_tau_mu[i] + Hb[i] - atlb_r;
            Buf0[i][32] = mv_r;
        }
        if (isdiag || isq0) { jn_r = Jb[16 + i]; hn_r = Hb[16 + i]; }
    }
    __syncwarp();

    float (*S)[48] = Buf0;
    float (*R)[48] = Buf1;

    // ======================= FORWARD =======================
    for (int t = 0; t < TM1; ++t) {
        float d0 = gj2<true>(S, R, 0,  i, j0, q);
        float d1 = gj2<true>(R, S, 2,  i, j0, q);
        float d2 = gj2<true>(S, R, 4,  i, j0, q);
        float d3 = gj2<true>(R, S, 6,  i, j0, q);
        float d4 = gj2<true>(S, R, 8,  i, j0, q);
        float d5 = gj2<true>(R, S, 10, i, j0, q);
        float d6 = gj2<true>(S, R, 12, i, j0, q);
        float d7 = gj2<true>(R, S, 14, i, j0, q);
        lzall += trans_const - 0.5f * (__logf(d0 * d1 * d2 * d3) + __logf(d4 * d5 * d6 * d7));

        const bool term = (t == TM1 - 1);
        {
            float tmp[8];
            ld8(&S[i][j0], tmp);       st8(&scr1[(size_t)t * 256 + i * 16 + j0], tmp);
            ld8(&S[i][16 + j0], tmp);  st8(&scr2[(size_t)t * 256 + i * 16 + j0], tmp);
        }

        float acc[8];
#pragma unroll
        for (int c = 0; c < 8; ++c) acc[c] = lam8[c];
#pragma unroll
        for (int k = 0; k < 16; ++k) {
            float a = sAtL[k][i];
            float s[8];
            ld8(&S[k][16 + j0], s);
#pragma unroll
            for (int c = 0; c < 8; ++c) acc[c] = fmaf(-a, s[c], acc[c]);
        }
        if (isdiag) {
            float jd = jn_r + 0.5f;
#pragma unroll
            for (int c = 0; c < 8; ++c) if (j0 + c == i) acc[c] += jd;
        }
        if (!term) {
#pragma unroll
            for (int c = 0; c < 8; ++c) acc[c] += atla8[c];
        }
        st8(&R[i][j0], acc);
        st8(&R[i][16 + j0], atl8);

        if (isq0) {
            float mim_i = S[i][32];
            scr3[(size_t)t * 16 + i] = mim_i;
            lzp += 0.5f * mv_r * mim_i;
            float s = lb_r + hn_r;
#pragma unroll
            for (int k = 0; k < 16; ++k) s = fmaf(sAtL[k][i], S[k][32], s);
            mv_r = term ? s : (s - atlb_r);
            R[i][32] = mv_r;
        }
        if ((isdiag || isq0) && (t + 2 < TT)) {
            jn_r = Jb[(t + 2) * 16 + i];
            hn_r = Hb[(t + 2) * 16 + i];
        }
        __syncwarp();
        float (*tmp)[48] = S; S = R; R = tmp;
    }

    // ---- terminal inversion ----
    {
        float d0 = gj2<true>(S, R, 0,  i, j0, q);
        float d1 = gj2<true>(R, S, 2,  i, j0, q);
        float d2 = gj2<true>(S, R, 4,  i, j0, q);
        float d3 = gj2<true>(R, S, 6,  i, j0, q);
        float d4 = gj2<true>(S, R, 8,  i, j0, q);
        float d5 = gj2<true>(R, S, 10, i, j0, q);
        float d6 = gj2<true>(S, R, 12, i, j0, q);
        float d7 = gj2<true>(R, S, 14, i, j0, q);
        lzall += init_const - 0.5f * (__logf(d0 * d1 * d2 * d3) + __logf(d4 * d5 * d6 * d7));
    }
    if (isq0) {
        float mT = S[i][32];
        mT_s[i] = mT;
        lzp += 0.5f * mv_r * mT;
        exO[(size_t)(TT - 1) * 16 + i] = mT;
        scr3[(size_t)TM1 * 16 + i]     = mT;
    }
    __syncwarp();
    {
        float vT[8], mTj[8], ex[8];
        ld8(&S[i][j0], vT);
        ld8(&mT_s[j0], mTj);
        float mTi = mT_s[i];
#pragma unroll
        for (int c = 0; c < 8; ++c) ex[c] = vT[c] + mTi * mTj[c];
        st8(&exxtO[(size_t)(TT - 1) * 256 + i * 16 + j0], ex);
        st8(&Vn[i][j0], vT);
        if (isdiag) {
            float vd = 0.f;
#pragma unroll
            for (int c = 0; c < 8; ++c) if (j0 + c == i) vd = vT[c];
            klacc += -0.5f * (jn_r + 0.5f) * (vd + mTi * mTi) + hn_r * mTi;
        }
        if (isq0) mn[i] = mT_s[i];
    }
    float g8p[8], pi8p[8];
    ld8(&scr2[(size_t)(TM1 - 1) * 256 + i * 16 + j0], g8p);
    ld8(&scr1[(size_t)(TM1 - 1) * 256 + i * 16 + j0], pi8p);
    float mim_r = 0.f;
    if (isq0)   mim_r = scr3[(size_t)(TM1 - 1) * 16 + i];
    if (isdiag || isq0) { jn_r = Jb[(TM1 - 1) * 16 + i]; hn_r = Hb[(TM1 - 1) * 16 + i]; }
    st8(&Gm[i][j0], g8p);
    __syncwarp();

    float v8_keep[8];
#pragma unroll
    for (int c = 0; c < 8; ++c) v8_keep[c] = 0.f;

    // ======================= BACKWARD =======================
    for (int t = TM1 - 1; t >= 0; --t) {
        // R2: Wb = G Vn ; mt
        float gmr[16];
        ld8(&Gm[i][0], gmr);
        ld8(&Gm[i][8], gmr + 8);
        float w8[8];
#pragma unroll
        for (int c = 0; c < 8; ++c) w8[c] = 0.f;
#pragma unroll
        for (int k = 0; k < 16; ++k) {
            float gk = gmr[k];
            float vk[8];
            ld8(&Vn[k][j0], vk);
#pragma unroll
            for (int c = 0; c < 8; ++c) w8[c] = fmaf(gk, vk[c], w8[c]);
        }
        st8(&Wb[i][j0], w8);
        if (isq0) {
            float s = mim_r;
#pragma unroll
            for (int k = 0; k < 16; ++k) s = fmaf(gmr[k], mn[k], s);
            mt_s[i] = s;
        }
        __syncwarp();                                      // b2

        // R3: Vt, outputs, stage GJ, klacc
        float wbr[16];
        ld8(&Wb[i][0], wbr);
        ld8(&Wb[i][8], wbr + 8);
        float v8[8];
#pragma unroll
        for (int c = 0; c < 8; ++c) {
            int row = j0 + c;
            float g[16];
            ld8(&Gm[row][0], g);
            ld8(&Gm[row][8], g + 8);
            float s = pi8p[c];
#pragma unroll
            for (int k = 0; k < 16; ++k) s = fmaf(wbr[k], g[k], s);
            v8[c] = s;
        }
#pragma unroll
        for (int c = 0; c < 8; ++c) v8_keep[c] = v8[c];
        float mti = mt_s[i];
        {
            float mtj[8], mnn[8], ex[8], en[8];
            ld8(&mt_s[j0], mtj);
            ld8(&mn[j0], mnn);
#pragma unroll
            for (int c = 0; c < 8; ++c) {
                ex[c] = v8[c] + mti * mtj[c];
                en[c] = w8[c] + mti * mnn[c];
            }
            st8(&exxtO [(size_t)t * 256 + i * 16 + j0], ex);
            st8(&exxntO[(size_t)t * 256 + i * 16 + j0], en);
        }
        if (isq0) {
            exO[(size_t)t * 16 + i]  = mti;
            scr3[(size_t)t * 16 + i] = mti;
        }
        if (isdiag) {
            float vd = 0.f;
#pragma unroll
            for (int c = 0; c < 8; ++c) if (j0 + c == i) vd = v8[c];
            klacc += -0.5f * (jn_r + 0.5f) * (vd + mti * mti) + hn_r * mti;
        }
        st8(&Buf0[i][j0], v8);
        st8(&Buf0[i][16 + j0], w8);
        __syncwarp();                                      // b3

        gj2<false>(Buf0, Buf1, 0,  i, j0, q);
        gj2<false>(Buf1, Buf0, 2,  i, j0, q);
        gj2<false>(Buf0, Buf1, 4,  i, j0, q);
        gj2<false>(Buf1, Buf0, 6,  i, j0, q);
        gj2<false>(Buf0, Buf1, 8,  i, j0, q);
        gj2<false>(Buf1, Buf0, 10, i, j0, q);
        gj2<false>(Buf0, Buf1, 12, i, j0, q);
        gj2<false>(Buf1, Buf0, 14, i, j0, q);
        // Buf0 = [Vt^{-1} | K]

        // R8: condV, K^T store, stage chol
        float c8[8];
        ld8(&Vn[i][j0], c8);
#pragma unroll
        for (int k = 0; k < 16; ++k) {
            float wk = Wb[k][i];
            float kk[8];
            ld8(&Buf0[k][16 + j0], kk);
#pragma unroll
            for (int c = 0; c < 8; ++c) c8[c] = fmaf(-wk, kk[c], c8[c]);
        }
        if (isdiag) {
#pragma unroll
            for (int c = 0; c < 8; ++c) if (j0 + c == i) c8[c] += 1e-6f;
        }
        {
            float kt[8];
#pragma unroll
            for (int c = 0; c < 8; ++c) kt[c] = Buf0[j0 + c][16 + i];
            st8(&scr1[(size_t)t * 256 + i * 16 + j0], kt);
        }
        st8(&Buf1[i][j0], c8);
        __syncwarp();                                      // b8

        chol2(Buf1, Buf0, 0,  i, j0);
        chol2(Buf0, Buf1, 2,  i, j0);
        chol2(Buf1, Buf0, 4,  i, j0);
        chol2(Buf0, Buf1, 6,  i, j0);
        chol2(Buf1, Buf0, 8,  i, j0);
        chol2(Buf0, Buf1, 10, i, j0);
        chol2(Buf1, Buf0, 12, i, j0);
        chol2(Buf0, Buf1, 14, i, j0);
        // Buf1 = Ls

        // last region: Ls store, carry, prefetch
        {
            float ls[8];
            ld8(&Buf1[i][j0], ls);
#pragma unroll
            for (int c = 0; c < 8; ++c) if (j0 + c > i) ls[c] = 0.f;
            st8(&scr2[(size_t)t * 256 + i * 16 + j0], ls);
        }
        st8(&Vn[i][j0], v8_keep);
        if (isq0) mn[i] = mt_s[i];
        if (t > 0) {
            ld8(&scr2[(size_t)(t - 1) * 256 + i * 16 + j0], g8p);
            ld8(&scr1[(size_t)(t - 1) * 256 + i * 16 + j0], pi8p);
            if (isq0)   mim_r = scr3[(size_t)(t - 1) * 16 + i];
            if (isdiag || isq0) { jn_r = Jb[(t - 1) * 16 + i]; hn_r = Hb[(t - 1) * 16 + i]; }
            st8(&Gm[i][j0], g8p);
        }
        __syncwarp();                                      // b1
    }

    // ======================= SAMPLING =======================
    {
        float v0[8];
#pragma unroll
        for (int c = 0; c < 8; ++c) v0[c] = v8_keep[c];
        if (isdiag) {
#pragma unroll
            for (int c = 0; c < 8; ++c) if (j0 + c == i) v0[c] += 1e-6f;
        }
        st8(&Buf0[i][j0], v0);
    }
    __syncwarp();
    chol2(Buf0, Buf1, 0,  i, j0);
    chol2(Buf1, Buf0, 2,  i, j0);
    chol2(Buf0, Buf1, 4,  i, j0);
    chol2(Buf1, Buf0, 6,  i, j0);
    chol2(Buf0, Buf1, 8,  i, j0);
    chol2(Buf1, Buf0, 10, i, j0);
    chol2(Buf0, Buf1, 12, i, j0);
    chol2(Buf1, Buf0, 14, i, j0);
    {
        float l8[8], e8[8];
        ld8(&Buf0[i][j0], l8);
        ld8(&epsb[j0], e8);
        float v = 0.f;
#pragma unroll
        for (int c = 0; c < 8; ++c) if (j0 + c <= i) v = fmaf(l8[c], e8[c], v);
        v += __shfl_xor_sync(0xffffffffu, v, 1);
        if (isq0) { float x = mn[i] + v; xs[0][i] = x; zO[i] = x; }
    }
    __syncwarp();

    float kt8[8], ls8[8], mtj8[8], ej8[8];
    ld8(&scr1[i * 16 + j0], kt8);
    ld8(&scr2[i * 16 + j0], ls8);
    ld8(&scr3[j0], mtj8);
    float mni = scr3[16 + i];
    ld8(&epsb[16 + j0], ej8);
    for (int t = 0; t < TM1; ++t) {
        float kt[8], ls[8], mtj[8], ej[8];
#pragma unroll
        for (int c = 0; c < 8; ++c) { kt[c]=kt8[c]; ls[c]=ls8[c]; mtj[c]=mtj8[c]; ej[c]=ej8[c]; }
        float mnc = mni;
        if (t + 1 < TM1) {
            ld8(&scr1[(size_t)(t + 1) * 256 + i * 16 + j0], kt8);
            ld8(&scr2[(size_t)(t + 1) * 256 + i * 16 + j0], ls8);
            ld8(&scr3[(size_t)(t + 1) * 16 + j0], mtj8);
            mni = scr3[(size_t)(t + 2) * 16 + i];
            ld8(&epsb[(size_t)(t + 2) * 16 + j0], ej8);
        }
        float x8[8];
        ld8(&xs[t & 1][j0], x8);
        float v = 0.f;
#pragma unroll
        for (int c = 0; c < 8; ++c) {
            v = fmaf(kt[c], x8[c] - mtj[c], v);
            v = fmaf(ls[c], ej[c], v);
        }
        v += __shfl_xor_sync(0xffffffffu, v, 1);
        if (isq0) {
            float x = mnc + v;
            xs[(t & 1) ^ 1][i] = x;
            zO[(size_t)(t + 1) * 16 + i] = x;
        }
        __syncwarp();
    }

    // ---- final reductions ----
    if (isdiag) red[i]      = klacc;
    if (isq0)   red[16 + i] = lzp;
    __syncwarp();
    if (tid == 0) {
        float kls = 0.f, lzs = 0.f;
#pragma unroll
        for (int k = 0; k < 16; ++k) { kls += red[k]; lzs += red[16 + k]; }
        out[KL_OFF + b] = kls - (lzall + lzs);
    }
}

extern "C" void kernel_launch(void* const* d_in, const int* in_sizes, int n_in,
                              void* d_out, int out_size) {
    const float* Jr    = (const float*)d_in[0];
    const float* hr    = (const float*)d_in[1];
    const float* loc   = (const float*)d_in[2];
    const float* Tau_p = (const float*)d_in[3];
    const float* Lam_p = (const float*)d_in[4];
    const float* X     = (const float*)d_in[5];
    float* out = (float*)d_out;

    setup_kernel<<<1, 256>>>(loc, Tau_p, Lam_p, X);
    lds_main<<<BB, 32>>>(Jr, hr, out);
}